// round 3
// baseline (speedup 1.0000x reference)
#include <cuda_runtime.h>
#include <stdint.h>

// Problem constants
#define NT    4000
#define NS    16
#define NR    512
#define NCOL  (NS * NR)          // 8192 columns
#define NCG   (NCOL / 4)         // 2048 float4 column-groups
#define NSEG  40
#define SEG_LEN (NT / NSEG)      // 100
#define TPB   256
#define XBLK  (NCG / TPB)        // 8 blocks in x
#define RED_BLOCKS (NCOL / TPB)  // 32

// Per-(segment, column) packed argmax: (float_bits(|v|max) << 32) | ~t
// u64 max => larger |v| wins; on tie, smaller t wins (matches jnp.argmax).
__device__ unsigned long long g_px[NSEG * NCOL];
__device__ unsigned long long g_py[NSEG * NCOL];
__device__ unsigned long long g_accum;
__device__ unsigned int       g_done;

// Kernel 1: grid (XBLK, NSEG). Each thread scans SEG_LEN time samples of 4
// adjacent columns (float4) for both x and y. Inner loop per element:
// FSETP(|v|, mx) + FMNMX(|v|, mx) + SEL(idx) -- 3 ops, no multiply.
__global__ __launch_bounds__(TPB) void seg_argmax_kernel(
    const float* __restrict__ x, const float* __restrict__ y)
{
    if (blockIdx.x == 0 && blockIdx.y == 0 && threadIdx.x == 0) {
        g_accum = 0ull;
        g_done  = 0u;
    }

    const int cg  = blockIdx.x * TPB + threadIdx.x;   // 0..NCG-1
    const int seg = blockIdx.y;
    const int t0  = seg * SEG_LEN;

    const float4* __restrict__ px =
        (const float4*)x + (size_t)t0 * NCG + cg;
    const float4* __restrict__ py =
        (const float4*)y + (size_t)t0 * NCG + cg;

    float mx0 = -1.f, mx1 = -1.f, mx2 = -1.f, mx3 = -1.f;
    float my0 = -1.f, my1 = -1.f, my2 = -1.f, my3 = -1.f;
    int ix0 = 0, ix1 = 0, ix2 = 0, ix3 = 0;
    int iy0 = 0, iy1 = 0, iy2 = 0, iy3 = 0;

    #pragma unroll 4
    for (int i = 0; i < SEG_LEN; ++i) {
        float4 vx = px[(size_t)i * NCG];
        float4 vy = py[(size_t)i * NCG];
        const int t = t0 + i;

        // x lanes
        if (fabsf(vx.x) > mx0) ix0 = t; mx0 = fmaxf(fabsf(vx.x), mx0);
        if (fabsf(vx.y) > mx1) ix1 = t; mx1 = fmaxf(fabsf(vx.y), mx1);
        if (fabsf(vx.z) > mx2) ix2 = t; mx2 = fmaxf(fabsf(vx.z), mx2);
        if (fabsf(vx.w) > mx3) ix3 = t; mx3 = fmaxf(fabsf(vx.w), mx3);
        // y lanes
        if (fabsf(vy.x) > my0) iy0 = t; my0 = fmaxf(fabsf(vy.x), my0);
        if (fabsf(vy.y) > my1) iy1 = t; my1 = fmaxf(fabsf(vy.y), my1);
        if (fabsf(vy.z) > my2) iy2 = t; my2 = fmaxf(fabsf(vy.z), my2);
        if (fabsf(vy.w) > my3) iy3 = t; my3 = fmaxf(fabsf(vy.w), my3);
    }

    const int colb = 4 * cg;
    unsigned long long* __restrict__ opx = g_px + (size_t)seg * NCOL + colb;
    unsigned long long* __restrict__ opy = g_py + (size_t)seg * NCOL + colb;

    opx[0] = ((unsigned long long)__float_as_uint(mx0) << 32) | (unsigned int)~ix0;
    opx[1] = ((unsigned long long)__float_as_uint(mx1) << 32) | (unsigned int)~ix1;
    opx[2] = ((unsigned long long)__float_as_uint(mx2) << 32) | (unsigned int)~ix2;
    opx[3] = ((unsigned long long)__float_as_uint(mx3) << 32) | (unsigned int)~ix3;
    opy[0] = ((unsigned long long)__float_as_uint(my0) << 32) | (unsigned int)~iy0;
    opy[1] = ((unsigned long long)__float_as_uint(my1) << 32) | (unsigned int)~iy1;
    opy[2] = ((unsigned long long)__float_as_uint(my2) << 32) | (unsigned int)~iy2;
    opy[3] = ((unsigned long long)__float_as_uint(my3) << 32) | (unsigned int)~iy3;
}

// Kernel 2: reduce over segments per column, MSE of index difference (exact
// int64), block reduce, one atomicAdd per block, last block finalizes.
__global__ __launch_bounds__(TPB) void reduce_mse_kernel(float* __restrict__ out)
{
    const int col = blockIdx.x * TPB + threadIdx.x;

    unsigned long long bx = 0ull, by = 0ull;
    #pragma unroll
    for (int s = 0; s < NSEG; ++s) {
        unsigned long long kx = g_px[(size_t)s * NCOL + col];
        unsigned long long ky = g_py[(size_t)s * NCOL + col];
        bx = (kx > bx) ? kx : bx;
        by = (ky > by) ? ky : by;
    }

    const int tx = (int)(~(unsigned int)bx);
    const int ty = (int)(~(unsigned int)by);
    const long long d = (long long)tx - (long long)ty;
    unsigned long long sq = (unsigned long long)(d * d);

    #pragma unroll
    for (int off = 16; off > 0; off >>= 1)
        sq += __shfl_down_sync(0xffffffffu, sq, off);

    __shared__ unsigned long long warp_sums[TPB / 32];
    __shared__ bool is_last;
    const int lane = threadIdx.x & 31;
    const int wid  = threadIdx.x >> 5;
    if (lane == 0) warp_sums[wid] = sq;
    __syncthreads();

    if (wid == 0) {
        unsigned long long v = (lane < TPB / 32) ? warp_sums[lane] : 0ull;
        #pragma unroll
        for (int off = 4; off > 0; off >>= 1)
            v += __shfl_down_sync(0xffffffffu, v, off);
        if (lane == 0) {
            atomicAdd(&g_accum, v);
            __threadfence();
            unsigned int ticket = atomicAdd(&g_done, 1u);
            is_last = (ticket == (unsigned int)(gridDim.x - 1));
        }
    }
    __syncthreads();

    if (is_last && threadIdx.x == 0) {
        unsigned long long total = atomicAdd(&g_accum, 0ull);
        out[0] = (float)((double)total / (double)NCOL);
    }
}

extern "C" void kernel_launch(void* const* d_in, const int* in_sizes, int n_in,
                              void* d_out, int out_size)
{
    const float* x = (const float*)d_in[0];
    const float* y = (const float*)d_in[1];
    float* out = (float*)d_out;

    dim3 grid1(XBLK, NSEG);
    seg_argmax_kernel<<<grid1, TPB>>>(x, y);
    reduce_mse_kernel<<<RED_BLOCKS, TPB>>>(out);
}